// round 5
// baseline (speedup 1.0000x reference)
#include <cuda_runtime.h>
#include <cuda_bf16.h>
#include <cstdint>

#define DFEAT 128
#define NMAX  50000
#define EMAX  600000
#define BM    64
#define LDSK  136      // smem row stride (bf16) -> 272B rows, 16B-mult, LDSM-friendly

// scratch (no allocations allowed) ------------------------------------------
__device__ __align__(16) float g_h[NMAX * DFEAT];     // dinv[src]-scaled features
__device__ __align__(16) float g_deg[NMAX];
__device__ __align__(16) float g_dinv[NMAX];
__device__ __align__(16) __nv_bfloat16 g_wh[128 * 128];
__device__ __align__(16) __nv_bfloat16 g_wl[128 * 128];
__device__ int g_cnt[NMAX];
__device__ int g_off[NMAX + 1];
__device__ int g_cur[NMAX];
__device__ int g_srcs[EMAX];

__device__ __forceinline__ void ldsm_x4(uint32_t addr, uint32_t& r0, uint32_t& r1,
                                        uint32_t& r2, uint32_t& r3) {
    asm volatile("ldmatrix.sync.aligned.m8n8.x4.shared.b16 {%0,%1,%2,%3}, [%4];"
                 : "=r"(r0), "=r"(r1), "=r"(r2), "=r"(r3) : "r"(addr));
}

__device__ __forceinline__ void mma_bf16(float c[4], const uint32_t a[4],
                                         uint32_t b0, uint32_t b1) {
    asm volatile("mma.sync.aligned.m16n8k16.row.col.f32.bf16.bf16.f32 "
                 "{%0,%1,%2,%3},{%4,%5,%6,%7},{%8,%9},{%0,%1,%2,%3};"
                 : "+f"(c[0]), "+f"(c[1]), "+f"(c[2]), "+f"(c[3])
                 : "r"(a[0]), "r"(a[1]), "r"(a[2]), "r"(a[3]), "r"(b0), "r"(b1));
}

__device__ __forceinline__ void cp_async16(uint32_t saddr, const void* gptr) {
    asm volatile("cp.async.ca.shared.global [%0], [%1], 16;"
                 :: "r"(saddr), "l"(gptr) : "memory");
}

// ---------------------------------------------------------------------------
__global__ void k_zero(int n_nodes) {
    int i = blockIdx.x * blockDim.x + threadIdx.x;
    if (i < n_nodes) { g_deg[i] = 0.f; g_cnt[i] = 0; }
}

// W -> bf16 hi/lo split (once)
__global__ void k_wsplit(const float* __restrict__ W) {
    int i = blockIdx.x * blockDim.x + threadIdx.x;
    if (i >= 128 * 128) return;
    float w = W[i];
    __nv_bfloat16 h = __float2bfloat16_rn(w);
    g_wh[i] = h;
    g_wl[i] = __float2bfloat16_rn(w - __bfloat162float(h));
}

__global__ void k_deg_hist(const int* __restrict__ ei, int E) {
    int e = blockIdx.x * blockDim.x + threadIdx.x;
    if (e >= E) return;
    int s = ei[e], d = ei[E + e];
    atomicAdd(&g_deg[s], 1.f);
    atomicAdd(&g_deg[d], 1.f);
    atomicAdd(&g_cnt[d], 1);
}

__global__ void k_dinv(int N) {
    int i = blockIdx.x * blockDim.x + threadIdx.x;
    if (i < N) g_dinv[i] = rsqrtf(fmaxf(g_deg[i], 1.0f));
}

// single-block exclusive scan of g_cnt -> g_off, g_cur
__global__ void k_scan(int N, int E) {
    __shared__ int part[1024];
    int t = threadIdx.x;
    int chunk = (N + 1023) >> 10;
    int beg = t * chunk, end = min(beg + chunk, N);
    int s = 0;
    for (int i = beg; i < end; i++) s += g_cnt[i];
    part[t] = s;
    __syncthreads();
    for (int off = 1; off < 1024; off <<= 1) {
        int v = (t >= off) ? part[t - off] : 0;
        __syncthreads();
        part[t] += v;
        __syncthreads();
    }
    int run = (t > 0) ? part[t - 1] : 0;
    for (int i = beg; i < end; i++) {
        int c = g_cnt[i];
        g_off[i] = run;
        g_cur[i] = run;
        run += c;
    }
    if (t == 1023) g_off[N] = E;
}

__global__ void k_fill(const int* __restrict__ ei, int E) {
    int e = blockIdx.x * blockDim.x + threadIdx.x;
    if (e >= E) return;
    int s = ei[e], d = ei[E + e];
    int slot = atomicAdd(&g_cur[d], 1);
    g_srcs[slot] = s;
}

// ---------------------------------------------------------------------------
// Fused logmap0 + GEMM + bias + dinv[row] scale (bf16-split tensor cores,
// cp.async W tiles, software-pipelined mainloop).
__global__ void __launch_bounds__(256, 2)
k_logmap_gemm(const float* __restrict__ x, const float* __restrict__ b, int N) {
    extern __shared__ __align__(16) char smraw[];
    __nv_bfloat16* swh = (__nv_bfloat16*)smraw;          // [128][LDSK]
    __nv_bfloat16* swl = swh + 128 * LDSK;
    __nv_bfloat16* sxh = swl + 128 * LDSK;               // [BM][LDSK]
    __nv_bfloat16* sxl = sxh + BM * LDSK;

    const int tid  = threadIdx.x;
    const int warp = tid >> 5, lane = tid & 31;
    const int row0 = blockIdx.x * BM;

    // ---- W tiles via cp.async (16B chunks; 2048 per buffer) ----
    {
        for (int c = tid; c < 2048; c += 256) {
            int row = c >> 4, col8 = (c & 15) * 8;
            uint32_t sh = (uint32_t)__cvta_generic_to_shared(&swh[row * LDSK + col8]);
            cp_async16(sh, &g_wh[row * 128 + col8]);
            uint32_t sl = (uint32_t)__cvta_generic_to_shared(&swl[row * LDSK + col8]);
            cp_async16(sl, &g_wl[row * 128 + col8]);
        }
        asm volatile("cp.async.commit_group;");
    }

    // ---- x rows: load, logmap0, split hi/lo (8 warps x 8 rows) ----
    {
        const float4* x4 = (const float4*)x;
#pragma unroll
        for (int rr = 0; rr < 8; rr++) {
            int r = warp * 8 + rr;
            int row = row0 + r;
            float4 v = (row < N) ? x4[row * 32 + lane] : make_float4(0.f, 0.f, 0.f, 0.f);
            float s = v.x * v.x + v.y * v.y + v.z * v.z + v.w * v.w;
#pragma unroll
            for (int off = 16; off; off >>= 1) s += __shfl_xor_sync(0xFFFFFFFFu, s, off);
            float norm = sqrtf(s);
            float nc = fminf(fmaxf(norm, 1e-15f), 1.0f - 1e-5f);
            float scale = atanhf(nc) / fmaxf(norm, 1e-15f);
            v.x *= scale; v.y *= scale; v.z *= scale; v.w *= scale;
            __nv_bfloat16 h0 = __float2bfloat16_rn(v.x), h1 = __float2bfloat16_rn(v.y);
            __nv_bfloat16 h2 = __float2bfloat16_rn(v.z), h3 = __float2bfloat16_rn(v.w);
            __nv_bfloat16 l0 = __float2bfloat16_rn(v.x - __bfloat162float(h0));
            __nv_bfloat16 l1 = __float2bfloat16_rn(v.y - __bfloat162float(h1));
            __nv_bfloat16 l2 = __float2bfloat16_rn(v.z - __bfloat162float(h2));
            __nv_bfloat16 l3 = __float2bfloat16_rn(v.w - __bfloat162float(h3));
            int kc = lane * 4;
            __nv_bfloat162 hh0; hh0.x = h0; hh0.y = h1;
            __nv_bfloat162 hh1; hh1.x = h2; hh1.y = h3;
            __nv_bfloat162 ll0; ll0.x = l0; ll0.y = l1;
            __nv_bfloat162 ll1; ll1.x = l2; ll1.y = l3;
            *(__nv_bfloat162*)&sxh[r * LDSK + kc]     = hh0;
            *(__nv_bfloat162*)&sxh[r * LDSK + kc + 2] = hh1;
            *(__nv_bfloat162*)&sxl[r * LDSK + kc]     = ll0;
            *(__nv_bfloat162*)&sxl[r * LDSK + kc + 2] = ll1;
        }
    }
    asm volatile("cp.async.wait_group 0;");
    __syncthreads();

    // ---- MMA mainloop (pipelined) ----
    const int wm = warp & 3;            // m 0..3
    const int wn = warp >> 2;           // n 0..1
    const int m0 = wm * 16;
    const int n0b = wn * 64;
    const int mat = lane >> 3, mr = lane & 7;

    // precompute LDSM base addresses
    const int arow = m0 + mr + 8 * (mat & 1);
    const int aoff = 8 * (mat >> 1);
    uint32_t aBaseH = (uint32_t)__cvta_generic_to_shared(&sxh[arow * LDSK + aoff]);
    uint32_t aBaseL = (uint32_t)__cvta_generic_to_shared(&sxl[arow * LDSK + aoff]);
    uint32_t bBaseH[4], bBaseL[4];
#pragma unroll
    for (int g = 0; g < 4; g++) {
        int nrow = n0b + g * 16 + mr + 8 * (mat >> 1);
        int koff = 8 * (mat & 1);
        bBaseH[g] = (uint32_t)__cvta_generic_to_shared(&swh[nrow * LDSK + koff]);
        bBaseL[g] = (uint32_t)__cvta_generic_to_shared(&swl[nrow * LDSK + koff]);
    }

    float acc[8][4];
#pragma unroll
    for (int f = 0; f < 8; f++)
#pragma unroll
        for (int j = 0; j < 4; j++) acc[f][j] = 0.f;

    uint32_t ah[2][4], al[2][4];
    uint32_t bh[2][4], bl[2][4];

    ldsm_x4(aBaseH, ah[0][0], ah[0][1], ah[0][2], ah[0][3]);
    ldsm_x4(aBaseL, al[0][0], al[0][1], al[0][2], al[0][3]);

#pragma unroll
    for (int kk = 0; kk < 8; kk++) {
        const uint32_t kb = kk * 32;           // byte offset per k-step (16 bf16)
        const int cur = kk & 1, nxt = cur ^ 1;
        ldsm_x4(bBaseH[0] + kb, bh[0][0], bh[0][1], bh[0][2], bh[0][3]);
        ldsm_x4(bBaseL[0] + kb, bl[0][0], bl[0][1], bl[0][2], bl[0][3]);
        if (kk < 7) {
            ldsm_x4(aBaseH + kb + 32, ah[nxt][0], ah[nxt][1], ah[nxt][2], ah[nxt][3]);
            ldsm_x4(aBaseL + kb + 32, al[nxt][0], al[nxt][1], al[nxt][2], al[nxt][3]);
        }
#pragma unroll
        for (int g = 0; g < 4; g++) {
            const int gb = g & 1, gn = gb ^ 1;
            if (g < 3) {
                ldsm_x4(bBaseH[g + 1] + kb, bh[gn][0], bh[gn][1], bh[gn][2], bh[gn][3]);
                ldsm_x4(bBaseL[g + 1] + kb, bl[gn][0], bl[gn][1], bl[gn][2], bl[gn][3]);
            }
#pragma unroll
            for (int o = 0; o < 2; o++) {
                const int f = 2 * g + o;
                uint32_t b0h = bh[gb][2 * o], b1h = bh[gb][2 * o + 1];
                uint32_t b0l = bl[gb][2 * o], b1l = bl[gb][2 * o + 1];
                mma_bf16(acc[f], ah[cur], b0h, b1h);
                mma_bf16(acc[f], ah[cur], b0l, b1l);
                mma_bf16(acc[f], al[cur], b0h, b1h);
                mma_bf16(acc[f], al[cur], b0l, b1l);
            }
        }
    }

    // ---- epilogue: +bias, *dinv[row], store float2 ----
    {
        int r0r = row0 + m0 + (lane >> 2);
        int r1r = r0r + 8;
        float di0 = (r0r < N) ? g_dinv[r0r] : 0.f;
        float di1 = (r1r < N) ? g_dinv[r1r] : 0.f;
        float2* h2p = (float2*)g_h;
#pragma unroll
        for (int f = 0; f < 8; f++) {
            int c = n0b + f * 8 + 2 * (lane & 3);
            float bx = b[c], by = b[c + 1];
            if (r0r < N) {
                float2 o0;
                o0.x = (acc[f][0] + bx) * di0;
                o0.y = (acc[f][1] + by) * di0;
                h2p[(r0r * DFEAT + c) >> 1] = o0;
            }
            if (r1r < N) {
                float2 o1;
                o1.x = (acc[f][2] + bx) * di1;
                o1.y = (acc[f][3] + by) * di1;
                h2p[(r1r * DFEAT + c) >> 1] = o1;
            }
        }
    }
}

// ---------------------------------------------------------------------------
// CSR gather-sum + dinv[dst] + expmap0, one warp per node. No atomics.
__global__ void k_gather(float* __restrict__ out, int N) {
    int gw = (blockIdx.x * blockDim.x + threadIdx.x) >> 5;
    int lane = threadIdx.x & 31;
    if (gw >= N) return;
    int beg = g_off[gw], end = g_off[gw + 1];
    const float4* h4 = (const float4*)g_h;

    float4 a0 = make_float4(0.f, 0.f, 0.f, 0.f);
    float4 a1 = make_float4(0.f, 0.f, 0.f, 0.f);
    int p = beg;
    for (; p + 2 <= end; p += 2) {
        int s0 = __ldg(&g_srcs[p]);
        int s1 = __ldg(&g_srcs[p + 1]);
        float4 v0 = h4[s0 * 32 + lane];
        float4 v1 = h4[s1 * 32 + lane];
        a0.x += v0.x; a0.y += v0.y; a0.z += v0.z; a0.w += v0.w;
        a1.x += v1.x; a1.y += v1.y; a1.z += v1.z; a1.w += v1.w;
    }
    if (p < end) {
        int s0 = __ldg(&g_srcs[p]);
        float4 v0 = h4[s0 * 32 + lane];
        a0.x += v0.x; a0.y += v0.y; a0.z += v0.z; a0.w += v0.w;
    }
    float di = g_dinv[gw];
    float4 acc;
    acc.x = (a0.x + a1.x) * di;
    acc.y = (a0.y + a1.y) * di;
    acc.z = (a0.z + a1.z) * di;
    acc.w = (a0.w + a1.w) * di;

    // expmap0
    float s = acc.x * acc.x + acc.y * acc.y + acc.z * acc.z + acc.w * acc.w;
#pragma unroll
    for (int off = 16; off; off >>= 1) s += __shfl_xor_sync(0xFFFFFFFFu, s, off);
    float norm = sqrtf(s);
    float scale = tanhf(norm) / fmaxf(norm, 1e-15f);
    acc.x *= scale; acc.y *= scale; acc.z *= scale; acc.w *= scale;
    ((float4*)out)[gw * 32 + lane] = acc;
}

// ---------------------------------------------------------------------------
extern "C" void kernel_launch(void* const* d_in, const int* in_sizes, int n_in,
                              void* d_out, int out_size) {
    const float* x  = (const float*)d_in[0];
    const int*   ei = (const int*)d_in[1];
    const float* W  = (const float*)d_in[2];
    const float* b  = (const float*)d_in[3];
    float* out = (float*)d_out;

    const int N = in_sizes[0] / DFEAT;
    const int E = in_sizes[1] / 2;

    k_zero<<<(N + 255) / 256, 256>>>(N);
    k_wsplit<<<(128 * 128 + 255) / 256, 256>>>(W);
    k_deg_hist<<<(E + 255) / 256, 256>>>(ei, E);
    k_dinv<<<(N + 255) / 256, 256>>>(N);
    k_scan<<<1, 1024>>>(N, E);
    k_fill<<<(E + 255) / 256, 256>>>(ei, E);
    {
        const int SMEM = (2 * 128 * LDSK + 2 * BM * LDSK) * (int)sizeof(__nv_bfloat16);
        cudaFuncSetAttribute(k_logmap_gemm,
                             cudaFuncAttributeMaxDynamicSharedMemorySize, SMEM);
        k_logmap_gemm<<<(N + BM - 1) / BM, 256, SMEM>>>(x, b, N);
    }
    {
        long long threads = (long long)N * 32;
        int grid = (int)((threads + 255) / 256);
        k_gather<<<grid, 256>>>(out, N);
    }
}

// round 6
// speedup vs baseline: 1.2923x; 1.2923x over previous
#include <cuda_runtime.h>
#include <cuda_bf16.h>
#include <cstdint>

#define DFEAT 128
#define NMAX  50000
#define BM    64
#define LDSK  136      // smem row stride (bf16) -> 272B rows, 16B-mult, LDSM-friendly

// scratch (no allocations allowed) ------------------------------------------
__device__ __align__(16) float g_h[NMAX * DFEAT];     // dinv[src]-scaled features
__device__ __align__(16) float g_deg[NMAX];
__device__ __align__(16) __nv_bfloat16 g_wh[128 * 128];
__device__ __align__(16) __nv_bfloat16 g_wl[128 * 128];

__device__ __forceinline__ void red_add_v4(float* addr, float4 v) {
    asm volatile("red.global.add.v4.f32 [%0], {%1,%2,%3,%4};"
                 :: "l"(addr), "f"(v.x), "f"(v.y), "f"(v.z), "f"(v.w)
                 : "memory");
}

__device__ __forceinline__ void ldsm_x4(uint32_t addr, uint32_t& r0, uint32_t& r1,
                                        uint32_t& r2, uint32_t& r3) {
    asm volatile("ldmatrix.sync.aligned.m8n8.x4.shared.b16 {%0,%1,%2,%3}, [%4];"
                 : "=r"(r0), "=r"(r1), "=r"(r2), "=r"(r3) : "r"(addr));
}

__device__ __forceinline__ void mma_bf16(float c[4], const uint32_t a[4],
                                         uint32_t b0, uint32_t b1) {
    asm volatile("mma.sync.aligned.m16n8k16.row.col.f32.bf16.bf16.f32 "
                 "{%0,%1,%2,%3},{%4,%5,%6,%7},{%8,%9},{%0,%1,%2,%3};"
                 : "+f"(c[0]), "+f"(c[1]), "+f"(c[2]), "+f"(c[3])
                 : "r"(a[0]), "r"(a[1]), "r"(a[2]), "r"(a[3]), "r"(b0), "r"(b1));
}

__device__ __forceinline__ void cp_async16(uint32_t saddr, const void* gptr) {
    asm volatile("cp.async.ca.shared.global [%0], [%1], 16;"
                 :: "r"(saddr), "l"(gptr) : "memory");
}

// ---------------------------------------------------------------------------
// init: zero out accumulator + degrees, and split W -> bf16 hi/lo (one pass)
__global__ void k_init(float* __restrict__ out, const float* __restrict__ W,
                       int n_out, int n_nodes) {
    int i = blockIdx.x * blockDim.x + threadIdx.x;
    int stride = gridDim.x * blockDim.x;
    for (int idx = i; idx < n_out; idx += stride) out[idx] = 0.f;
    for (int idx = i; idx < n_nodes; idx += stride) g_deg[idx] = 0.f;
    for (int idx = i; idx < 128 * 128; idx += stride) {
        float w = W[idx];
        __nv_bfloat16 h = __float2bfloat16_rn(w);
        g_wh[idx] = h;
        g_wl[idx] = __float2bfloat16_rn(w - __bfloat162float(h));
    }
}

__global__ void k_degree(const int* __restrict__ ei, int E) {
    int e = blockIdx.x * blockDim.x + threadIdx.x;
    if (e >= E) return;
    atomicAdd(&g_deg[ei[e]], 1.f);       // src
    atomicAdd(&g_deg[ei[E + e]], 1.f);   // dst
}

// ---------------------------------------------------------------------------
// Fused logmap0 + GEMM + bias + dinv[row] scale (bf16-split tensor cores,
// cp.async W tiles, software-pipelined mainloop). dinv computed on the fly.
__global__ void __launch_bounds__(256, 2)
k_logmap_gemm(const float* __restrict__ x, const float* __restrict__ b, int N) {
    extern __shared__ __align__(16) char smraw[];
    __nv_bfloat16* swh = (__nv_bfloat16*)smraw;          // [128][LDSK]
    __nv_bfloat16* swl = swh + 128 * LDSK;
    __nv_bfloat16* sxh = swl + 128 * LDSK;               // [BM][LDSK]
    __nv_bfloat16* sxl = sxh + BM * LDSK;

    const int tid  = threadIdx.x;
    const int warp = tid >> 5, lane = tid & 31;
    const int row0 = blockIdx.x * BM;

    // ---- W tiles via cp.async (16B chunks) ----
    {
        for (int c = tid; c < 2048; c += 256) {
            int row = c >> 4, col8 = (c & 15) * 8;
            uint32_t sh = (uint32_t)__cvta_generic_to_shared(&swh[row * LDSK + col8]);
            cp_async16(sh, &g_wh[row * 128 + col8]);
            uint32_t sl = (uint32_t)__cvta_generic_to_shared(&swl[row * LDSK + col8]);
            cp_async16(sl, &g_wl[row * 128 + col8]);
        }
        asm volatile("cp.async.commit_group;");
    }

    // ---- x rows: load, logmap0, split hi/lo (8 warps x 8 rows) ----
    {
        const float4* x4 = (const float4*)x;
#pragma unroll
        for (int rr = 0; rr < 8; rr++) {
            int r = warp * 8 + rr;
            int row = row0 + r;
            float4 v = (row < N) ? x4[row * 32 + lane] : make_float4(0.f, 0.f, 0.f, 0.f);
            float s = v.x * v.x + v.y * v.y + v.z * v.z + v.w * v.w;
#pragma unroll
            for (int off = 16; off; off >>= 1) s += __shfl_xor_sync(0xFFFFFFFFu, s, off);
            float norm = sqrtf(s);
            float nc = fminf(fmaxf(norm, 1e-15f), 1.0f - 1e-5f);
            float scale = atanhf(nc) / fmaxf(norm, 1e-15f);
            v.x *= scale; v.y *= scale; v.z *= scale; v.w *= scale;
            __nv_bfloat16 h0 = __float2bfloat16_rn(v.x), h1 = __float2bfloat16_rn(v.y);
            __nv_bfloat16 h2 = __float2bfloat16_rn(v.z), h3 = __float2bfloat16_rn(v.w);
            __nv_bfloat16 l0 = __float2bfloat16_rn(v.x - __bfloat162float(h0));
            __nv_bfloat16 l1 = __float2bfloat16_rn(v.y - __bfloat162float(h1));
            __nv_bfloat16 l2 = __float2bfloat16_rn(v.z - __bfloat162float(h2));
            __nv_bfloat16 l3 = __float2bfloat16_rn(v.w - __bfloat162float(h3));
            int kc = lane * 4;
            __nv_bfloat162 hh0; hh0.x = h0; hh0.y = h1;
            __nv_bfloat162 hh1; hh1.x = h2; hh1.y = h3;
            __nv_bfloat162 ll0; ll0.x = l0; ll0.y = l1;
            __nv_bfloat162 ll1; ll1.x = l2; ll1.y = l3;
            *(__nv_bfloat162*)&sxh[r * LDSK + kc]     = hh0;
            *(__nv_bfloat162*)&sxh[r * LDSK + kc + 2] = hh1;
            *(__nv_bfloat162*)&sxl[r * LDSK + kc]     = ll0;
            *(__nv_bfloat162*)&sxl[r * LDSK + kc + 2] = ll1;
        }
    }
    asm volatile("cp.async.wait_group 0;");
    __syncthreads();

    // ---- MMA mainloop (pipelined) ----
    const int wm = warp & 3;            // m 0..3
    const int wn = warp >> 2;           // n 0..1
    const int m0 = wm * 16;
    const int n0b = wn * 64;
    const int mat = lane >> 3, mr = lane & 7;

    const int arow = m0 + mr + 8 * (mat & 1);
    const int aoff = 8 * (mat >> 1);
    uint32_t aBaseH = (uint32_t)__cvta_generic_to_shared(&sxh[arow * LDSK + aoff]);
    uint32_t aBaseL = (uint32_t)__cvta_generic_to_shared(&sxl[arow * LDSK + aoff]);
    uint32_t bBaseH[4], bBaseL[4];
#pragma unroll
    for (int g = 0; g < 4; g++) {
        int nrow = n0b + g * 16 + mr + 8 * (mat >> 1);
        int koff = 8 * (mat & 1);
        bBaseH[g] = (uint32_t)__cvta_generic_to_shared(&swh[nrow * LDSK + koff]);
        bBaseL[g] = (uint32_t)__cvta_generic_to_shared(&swl[nrow * LDSK + koff]);
    }

    float acc[8][4];
#pragma unroll
    for (int f = 0; f < 8; f++)
#pragma unroll
        for (int j = 0; j < 4; j++) acc[f][j] = 0.f;

    uint32_t ah[2][4], al[2][4];
    uint32_t bh[2][4], bl[2][4];

    ldsm_x4(aBaseH, ah[0][0], ah[0][1], ah[0][2], ah[0][3]);
    ldsm_x4(aBaseL, al[0][0], al[0][1], al[0][2], al[0][3]);

#pragma unroll
    for (int kk = 0; kk < 8; kk++) {
        const uint32_t kb = kk * 32;           // byte offset per k-step (16 bf16)
        const int cur = kk & 1, nxt = cur ^ 1;
        ldsm_x4(bBaseH[0] + kb, bh[0][0], bh[0][1], bh[0][2], bh[0][3]);
        ldsm_x4(bBaseL[0] + kb, bl[0][0], bl[0][1], bl[0][2], bl[0][3]);
        if (kk < 7) {
            ldsm_x4(aBaseH + kb + 32, ah[nxt][0], ah[nxt][1], ah[nxt][2], ah[nxt][3]);
            ldsm_x4(aBaseL + kb + 32, al[nxt][0], al[nxt][1], al[nxt][2], al[nxt][3]);
        }
#pragma unroll
        for (int g = 0; g < 4; g++) {
            const int gb = g & 1, gn = gb ^ 1;
            if (g < 3) {
                ldsm_x4(bBaseH[g + 1] + kb, bh[gn][0], bh[gn][1], bh[gn][2], bh[gn][3]);
                ldsm_x4(bBaseL[g + 1] + kb, bl[gn][0], bl[gn][1], bl[gn][2], bl[gn][3]);
            }
#pragma unroll
            for (int o = 0; o < 2; o++) {
                const int f = 2 * g + o;
                uint32_t b0h = bh[gb][2 * o], b1h = bh[gb][2 * o + 1];
                uint32_t b0l = bl[gb][2 * o], b1l = bl[gb][2 * o + 1];
                mma_bf16(acc[f], ah[cur], b0h, b1h);
                mma_bf16(acc[f], ah[cur], b0l, b1l);
                mma_bf16(acc[f], al[cur], b0h, b1h);
                mma_bf16(acc[f], al[cur], b0l, b1l);
            }
        }
    }

    // ---- epilogue: +bias, *rsqrt(deg[row]), store float2 ----
    {
        int r0r = row0 + m0 + (lane >> 2);
        int r1r = r0r + 8;
        float di0 = (r0r < N) ? rsqrtf(fmaxf(g_deg[r0r], 1.0f)) : 0.f;
        float di1 = (r1r < N) ? rsqrtf(fmaxf(g_deg[r1r], 1.0f)) : 0.f;
        float2* h2p = (float2*)g_h;
#pragma unroll
        for (int f = 0; f < 8; f++) {
            int c = n0b + f * 8 + 2 * (lane & 3);
            float bx = b[c], by = b[c + 1];
            if (r0r < N) {
                float2 o0;
                o0.x = (acc[f][0] + bx) * di0;
                o0.y = (acc[f][1] + by) * di0;
                h2p[(r0r * DFEAT + c) >> 1] = o0;
            }
            if (r1r < N) {
                float2 o1;
                o1.x = (acc[f][2] + bx) * di1;
                o1.y = (acc[f][3] + by) * di1;
                h2p[(r1r * DFEAT + c) >> 1] = o1;
            }
        }
    }
}

// ---------------------------------------------------------------------------
// Edge scatter: one warp per edge. lane = one float4 of the 128-dim feature.
// h is pre-scaled by dinv[src]; dinv[dst] computed on the fly (1 MUFU/warp).
__global__ void k_scatter(const int* __restrict__ ei, float* __restrict__ out, int E) {
    int gw = (blockIdx.x * blockDim.x + threadIdx.x) >> 5;
    int lane = threadIdx.x & 31;
    if (gw >= E) return;
    int src = __ldg(&ei[gw]);
    int dst = __ldg(&ei[E + gw]);
    float coef = rsqrtf(fmaxf(g_deg[dst], 1.0f));
    const float4* h4 = (const float4*)g_h;
    float4 v = h4[src * 32 + lane];
    v.x *= coef; v.y *= coef; v.z *= coef; v.w *= coef;
    float4* o4 = (float4*)out;
    red_add_v4((float*)&o4[dst * 32 + lane], v);
}

// ---------------------------------------------------------------------------
// expmap0 in-place on out: one warp per node.
__global__ void k_expmap(float* __restrict__ out, int N) {
    int gw = (blockIdx.x * blockDim.x + threadIdx.x) >> 5;
    int lane = threadIdx.x & 31;
    if (gw >= N) return;
    float4* o4 = (float4*)out;
    float4 v = o4[gw * 32 + lane];
    float s = v.x * v.x + v.y * v.y + v.z * v.z + v.w * v.w;
#pragma unroll
    for (int off = 16; off; off >>= 1) s += __shfl_xor_sync(0xFFFFFFFFu, s, off);
    float norm = sqrtf(s);
    float scale = tanhf(norm) / fmaxf(norm, 1e-15f);
    v.x *= scale; v.y *= scale; v.z *= scale; v.w *= scale;
    o4[gw * 32 + lane] = v;
}

// ---------------------------------------------------------------------------
extern "C" void kernel_launch(void* const* d_in, const int* in_sizes, int n_in,
                              void* d_out, int out_size) {
    const float* x  = (const float*)d_in[0];
    const int*   ei = (const int*)d_in[1];
    const float* W  = (const float*)d_in[2];
    const float* b  = (const float*)d_in[3];
    float* out = (float*)d_out;

    const int N = in_sizes[0] / DFEAT;
    const int E = in_sizes[1] / 2;

    // 1. zero out + deg, split W (fused)
    {
        int n_out = N * DFEAT;
        k_init<<<(n_out + 255) / 256, 256>>>(out, W, n_out, N);
    }
    // 2. degrees
    k_degree<<<(E + 255) / 256, 256>>>(ei, E);
    // 3. logmap0 + GEMM (+bias, *dinv[row]) -> g_h
    {
        const int SMEM = (2 * 128 * LDSK + 2 * BM * LDSK) * (int)sizeof(__nv_bfloat16);
        cudaFuncSetAttribute(k_logmap_gemm,
                             cudaFuncAttributeMaxDynamicSharedMemorySize, SMEM);
        k_logmap_gemm<<<(N + BM - 1) / BM, 256, SMEM>>>(x, b, N);
    }
    // 4. gather-scale-scatter over edges (warp per edge, vec4 red)
    {
        long long threads = (long long)E * 32;
        int grid = (int)((threads + 255) / 256);
        k_scatter<<<grid, 256>>>(ei, out, E);
    }
    // 5. expmap0 in place
    k_expmap<<<(N + 7) / 8, 256>>>(out, N);
}

// round 7
// speedup vs baseline: 1.8627x; 1.4414x over previous
#include <cuda_runtime.h>
#include <cuda_bf16.h>
#include <cstdint>

#define DFEAT 128
#define NMAX  50000
#define NPAD  50176      // 49 * 1024, covers NMAX
#define EMAX  600000
#define BM    64
#define LDSK  136        // smem row stride (bf16) -> 272B rows

// scratch (no allocations allowed) ------------------------------------------
__device__ __align__(16) float g_h[NMAX * DFEAT];     // dinv[src]-scaled features
__device__ __align__(16) int   g_cin[NPAD];           // in-degree  (CSR counts)
__device__ __align__(16) int   g_cout[NPAD];          // out-degree
__device__ __align__(16) int   g_off[NPAD + 1];
__device__ __align__(16) int   g_cur[NPAD];
__device__ __align__(16) int   g_srcs[EMAX];
__device__ __align__(16) int   g_bsum[64];
__device__ __align__(16) int   g_boff[64];
__device__ __align__(16) __nv_bfloat16 g_wh[128 * 128];
__device__ __align__(16) __nv_bfloat16 g_wl[128 * 128];

__device__ __forceinline__ void ldsm_x4(uint32_t addr, uint32_t& r0, uint32_t& r1,
                                        uint32_t& r2, uint32_t& r3) {
    asm volatile("ldmatrix.sync.aligned.m8n8.x4.shared.b16 {%0,%1,%2,%3}, [%4];"
                 : "=r"(r0), "=r"(r1), "=r"(r2), "=r"(r3) : "r"(addr));
}

__device__ __forceinline__ void mma_bf16(float c[4], const uint32_t a[4],
                                         uint32_t b0, uint32_t b1) {
    asm volatile("mma.sync.aligned.m16n8k16.row.col.f32.bf16.bf16.f32 "
                 "{%0,%1,%2,%3},{%4,%5,%6,%7},{%8,%9},{%0,%1,%2,%3};"
                 : "+f"(c[0]), "+f"(c[1]), "+f"(c[2]), "+f"(c[3])
                 : "r"(a[0]), "r"(a[1]), "r"(a[2]), "r"(a[3]), "r"(b0), "r"(b1));
}

__device__ __forceinline__ void cp_async16(uint32_t saddr, const void* gptr) {
    asm volatile("cp.async.ca.shared.global [%0], [%1], 16;"
                 :: "r"(saddr), "l"(gptr) : "memory");
}

// ---------------------------------------------------------------------------
// init: zero degree counters (padded) + split W -> bf16 hi/lo
__global__ void k_init(const float* __restrict__ W) {
    int i = blockIdx.x * blockDim.x + threadIdx.x;
    int stride = gridDim.x * blockDim.x;
    for (int idx = i; idx < NPAD; idx += stride) { g_cin[idx] = 0; g_cout[idx] = 0; }
    for (int idx = i; idx < 128 * 128; idx += stride) {
        float w = W[idx];
        __nv_bfloat16 h = __float2bfloat16_rn(w);
        g_wh[idx] = h;
        g_wl[idx] = __float2bfloat16_rn(w - __bfloat162float(h));
    }
}

__global__ void k_count(const int* __restrict__ ei, int E) {
    int e = blockIdx.x * blockDim.x + threadIdx.x;
    if (e >= E) return;
    atomicAdd(&g_cout[ei[e]], 1);        // src out-degree
    atomicAdd(&g_cin[ei[E + e]], 1);     // dst in-degree (= CSR count)
}

// ---- two-level exclusive scan of g_cin -> g_off --------------------------
// A: 49 blocks x 256 thr, 4 elems/thr (block = 1024 elems)
__global__ void k_scanA() {
    __shared__ int woff[8];
    int blk = blockIdx.x, t = threadIdx.x;
    int lane = t & 31, w = t >> 5;
    int base = blk * 1024 + t * 4;
    int4 c = *(const int4*)&g_cin[base];
    int s = c.x + c.y + c.z + c.w;
    int v = s;
#pragma unroll
    for (int off = 1; off < 32; off <<= 1) {
        int u = __shfl_up_sync(0xFFFFFFFFu, v, off);
        if (lane >= off) v += u;
    }
    if (lane == 31) woff[w] = v;
    __syncthreads();
    if (t == 0) {
        int run = 0;
#pragma unroll
        for (int i = 0; i < 8; i++) { int x = woff[i]; woff[i] = run; run += x; }
        g_bsum[blk] = run;
    }
    __syncthreads();
    int run = (v - s) + woff[w];            // exclusive prefix of first element
    g_off[base]     = run; run += c.x;
    g_off[base + 1] = run; run += c.y;
    g_off[base + 2] = run; run += c.z;
    g_off[base + 3] = run;
}

// B: scan 49 block sums (trivial)
__global__ void k_scanB(int nb) {
    if (threadIdx.x == 0) {
        int run = 0;
        for (int i = 0; i < nb; i++) { int x = g_bsum[i]; g_boff[i] = run; run += x; }
    }
}

// C: add block offsets, init cursors, set sentinel
__global__ void k_scanC(int E) {
    int i = blockIdx.x * blockDim.x + threadIdx.x;
    if (i < NPAD) {
        int o = g_off[i] + g_boff[i >> 10];
        g_off[i] = o;
        g_cur[i] = o;
    }
    if (i == 0) g_off[NPAD] = E;
}

__global__ void k_fill(const int* __restrict__ ei, int E) {
    int e = blockIdx.x * blockDim.x + threadIdx.x;
    if (e >= E) return;
    int s = ei[e], d = ei[E + e];
    int slot = atomicAdd(&g_cur[d], 1);
    g_srcs[slot] = s;
}

// ---------------------------------------------------------------------------
// Fused logmap0 + GEMM + bias + dinv[row] scale (bf16-split tensor cores,
// cp.async W tiles, pipelined LDSM/MMA mainloop).
__global__ void __launch_bounds__(256, 2)
k_logmap_gemm(const float* __restrict__ x, const float* __restrict__ b, int N) {
    extern __shared__ __align__(16) char smraw[];
    __nv_bfloat16* swh = (__nv_bfloat16*)smraw;          // [128][LDSK]
    __nv_bfloat16* swl = swh + 128 * LDSK;
    __nv_bfloat16* sxh = swl + 128 * LDSK;               // [BM][LDSK]
    __nv_bfloat16* sxl = sxh + BM * LDSK;

    const int tid  = threadIdx.x;
    const int warp = tid >> 5, lane = tid & 31;
    const int row0 = blockIdx.x * BM;

    // ---- W tiles via cp.async ----
    {
        for (int c = tid; c < 2048; c += 256) {
            int row = c >> 4, col8 = (c & 15) * 8;
            uint32_t sh = (uint32_t)__cvta_generic_to_shared(&swh[row * LDSK + col8]);
            cp_async16(sh, &g_wh[row * 128 + col8]);
            uint32_t sl = (uint32_t)__cvta_generic_to_shared(&swl[row * LDSK + col8]);
            cp_async16(sl, &g_wl[row * 128 + col8]);
        }
        asm volatile("cp.async.commit_group;");
    }

    // ---- x rows: load, logmap0, split hi/lo ----
    {
        const float4* x4 = (const float4*)x;
#pragma unroll
        for (int rr = 0; rr < 8; rr++) {
            int r = warp * 8 + rr;
            int row = row0 + r;
            float4 v = (row < N) ? x4[row * 32 + lane] : make_float4(0.f, 0.f, 0.f, 0.f);
            float s = v.x * v.x + v.y * v.y + v.z * v.z + v.w * v.w;
#pragma unroll
            for (int off = 16; off; off >>= 1) s += __shfl_xor_sync(0xFFFFFFFFu, s, off);
            float norm = sqrtf(s);
            float nc = fminf(fmaxf(norm, 1e-15f), 1.0f - 1e-5f);
            float scale = atanhf(nc) / fmaxf(norm, 1e-15f);
            v.x *= scale; v.y *= scale; v.z *= scale; v.w *= scale;
            __nv_bfloat16 h0 = __float2bfloat16_rn(v.x), h1 = __float2bfloat16_rn(v.y);
            __nv_bfloat16 h2 = __float2bfloat16_rn(v.z), h3 = __float2bfloat16_rn(v.w);
            __nv_bfloat16 l0 = __float2bfloat16_rn(v.x - __bfloat162float(h0));
            __nv_bfloat16 l1 = __float2bfloat16_rn(v.y - __bfloat162float(h1));
            __nv_bfloat16 l2 = __float2bfloat16_rn(v.z - __bfloat162float(h2));
            __nv_bfloat16 l3 = __float2bfloat16_rn(v.w - __bfloat162float(h3));
            int kc = lane * 4;
            __nv_bfloat162 hh0; hh0.x = h0; hh0.y = h1;
            __nv_bfloat162 hh1; hh1.x = h2; hh1.y = h3;
            __nv_bfloat162 ll0; ll0.x = l0; ll0.y = l1;
            __nv_bfloat162 ll1; ll1.x = l2; ll1.y = l3;
            *(__nv_bfloat162*)&sxh[r * LDSK + kc]     = hh0;
            *(__nv_bfloat162*)&sxh[r * LDSK + kc + 2] = hh1;
            *(__nv_bfloat162*)&sxl[r * LDSK + kc]     = ll0;
            *(__nv_bfloat162*)&sxl[r * LDSK + kc + 2] = ll1;
        }
    }
    asm volatile("cp.async.wait_group 0;");
    __syncthreads();

    // ---- MMA mainloop (pipelined) ----
    const int wm = warp & 3, wn = warp >> 2;
    const int m0 = wm * 16, n0b = wn * 64;
    const int mat = lane >> 3, mr = lane & 7;

    const int arow = m0 + mr + 8 * (mat & 1);
    const int aoff = 8 * (mat >> 1);
    uint32_t aBaseH = (uint32_t)__cvta_generic_to_shared(&sxh[arow * LDSK + aoff]);
    uint32_t aBaseL = (uint32_t)__cvta_generic_to_shared(&sxl[arow * LDSK + aoff]);
    uint32_t bBaseH[4], bBaseL[4];
#pragma unroll
    for (int g = 0; g < 4; g++) {
        int nrow = n0b + g * 16 + mr + 8 * (mat >> 1);
        int koff = 8 * (mat & 1);
        bBaseH[g] = (uint32_t)__cvta_generic_to_shared(&swh[nrow * LDSK + koff]);
        bBaseL[g] = (uint32_t)__cvta_generic_to_shared(&swl[nrow * LDSK + koff]);
    }

    float acc[8][4];
#pragma unroll
    for (int f = 0; f < 8; f++)
#pragma unroll
        for (int j = 0; j < 4; j++) acc[f][j] = 0.f;

    uint32_t ah[2][4], al[2][4];
    uint32_t bh[2][4], bl[2][4];

    ldsm_x4(aBaseH, ah[0][0], ah[0][1], ah[0][2], ah[0][3]);
    ldsm_x4(aBaseL, al[0][0], al[0][1], al[0][2], al[0][3]);

#pragma unroll
    for (int kk = 0; kk < 8; kk++) {
        const uint32_t kb = kk * 32;
        const int cur = kk & 1, nxt = cur ^ 1;
        ldsm_x4(bBaseH[0] + kb, bh[0][0], bh[0][1], bh[0][2], bh[0][3]);
        ldsm_x4(bBaseL[0] + kb, bl[0][0], bl[0][1], bl[0][2], bl[0][3]);
        if (kk < 7) {
            ldsm_x4(aBaseH + kb + 32, ah[nxt][0], ah[nxt][1], ah[nxt][2], ah[nxt][3]);
            ldsm_x4(aBaseL + kb + 32, al[nxt][0], al[nxt][1], al[nxt][2], al[nxt][3]);
        }
#pragma unroll
        for (int g = 0; g < 4; g++) {
            const int gb = g & 1, gn = gb ^ 1;
            if (g < 3) {
                ldsm_x4(bBaseH[g + 1] + kb, bh[gn][0], bh[gn][1], bh[gn][2], bh[gn][3]);
                ldsm_x4(bBaseL[g + 1] + kb, bl[gn][0], bl[gn][1], bl[gn][2], bl[gn][3]);
            }
#pragma unroll
            for (int o = 0; o < 2; o++) {
                const int f = 2 * g + o;
                uint32_t b0h = bh[gb][2 * o], b1h = bh[gb][2 * o + 1];
                uint32_t b0l = bl[gb][2 * o], b1l = bl[gb][2 * o + 1];
                mma_bf16(acc[f], ah[cur], b0h, b1h);
                mma_bf16(acc[f], ah[cur], b0l, b1l);
                mma_bf16(acc[f], al[cur], b0h, b1h);
                mma_bf16(acc[f], al[cur], b0l, b1l);
            }
        }
    }

    // ---- epilogue: +bias, *rsqrt(deg), store ----
    {
        int r0r = row0 + m0 + (lane >> 2);
        int r1r = r0r + 8;
        float di0 = 0.f, di1 = 0.f;
        if (r0r < N) di0 = rsqrtf(fmaxf((float)(g_cin[r0r] + g_cout[r0r]), 1.0f));
        if (r1r < N) di1 = rsqrtf(fmaxf((float)(g_cin[r1r] + g_cout[r1r]), 1.0f));
        float2* h2p = (float2*)g_h;
#pragma unroll
        for (int f = 0; f < 8; f++) {
            int c = n0b + f * 8 + 2 * (lane & 3);
            float bx = b[c], by = b[c + 1];
            if (r0r < N) {
                float2 o0;
                o0.x = (acc[f][0] + bx) * di0;
                o0.y = (acc[f][1] + by) * di0;
                h2p[(r0r * DFEAT + c) >> 1] = o0;
            }
            if (r1r < N) {
                float2 o1;
                o1.x = (acc[f][2] + bx) * di1;
                o1.y = (acc[f][3] + by) * di1;
                h2p[(r1r * DFEAT + c) >> 1] = o1;
            }
        }
    }
}

// ---------------------------------------------------------------------------
// CSR gather-sum + dinv[dst] + expmap0, one warp per node. No atomics.
__global__ void k_gather(float* __restrict__ out, int N) {
    int gw = (blockIdx.x * blockDim.x + threadIdx.x) >> 5;
    int lane = threadIdx.x & 31;
    if (gw >= N) return;
    int beg = g_off[gw], end = g_off[gw + 1];
    const float4* h4 = (const float4*)g_h;

    float4 a0 = make_float4(0.f, 0.f, 0.f, 0.f);
    float4 a1 = make_float4(0.f, 0.f, 0.f, 0.f);
    int p = beg;
    for (; p + 2 <= end; p += 2) {
        int s0 = __ldg(&g_srcs[p]);
        int s1 = __ldg(&g_srcs[p + 1]);
        float4 v0 = h4[s0 * 32 + lane];
        float4 v1 = h4[s1 * 32 + lane];
        a0.x += v0.x; a0.y += v0.y; a0.z += v0.z; a0.w += v0.w;
        a1.x += v1.x; a1.y += v1.y; a1.z += v1.z; a1.w += v1.w;
    }
    if (p < end) {
        int s0 = __ldg(&g_srcs[p]);
        float4 v0 = h4[s0 * 32 + lane];
        a0.x += v0.x; a0.y += v0.y; a0.z += v0.z; a0.w += v0.w;
    }
    float di = rsqrtf(fmaxf((float)(g_cin[gw] + g_cout[gw]), 1.0f));
    float4 acc;
    acc.x = (a0.x + a1.x) * di;
    acc.y = (a0.y + a1.y) * di;
    acc.z = (a0.z + a1.z) * di;
    acc.w = (a0.w + a1.w) * di;

    // expmap0
    float s = acc.x * acc.x + acc.y * acc.y + acc.z * acc.z + acc.w * acc.w;
#pragma unroll
    for (int off = 16; off; off >>= 1) s += __shfl_xor_sync(0xFFFFFFFFu, s, off);
    float norm = sqrtf(s);
    float scale = tanhf(norm) / fmaxf(norm, 1e-15f);
    acc.x *= scale; acc.y *= scale; acc.z *= scale; acc.w *= scale;
    ((float4*)out)[gw * 32 + lane] = acc;
}

// ---------------------------------------------------------------------------
extern "C" void kernel_launch(void* const* d_in, const int* in_sizes, int n_in,
                              void* d_out, int out_size) {
    const float* x  = (const float*)d_in[0];
    const int*   ei = (const int*)d_in[1];
    const float* W  = (const float*)d_in[2];
    const float* b  = (const float*)d_in[3];
    float* out = (float*)d_out;

    const int N = in_sizes[0] / DFEAT;
    const int E = in_sizes[1] / 2;
    const int NB = (NPAD + 1023) / 1024;   // 49 scan blocks

    k_init<<<(NPAD + 255) / 256, 256>>>(W);
    k_count<<<(E + 255) / 256, 256>>>(ei, E);
    k_scanA<<<NB, 256>>>();
    k_scanB<<<1, 32>>>(NB);
    k_scanC<<<(NPAD + 255) / 256, 256>>>(E);
    k_fill<<<(E + 255) / 256, 256>>>(ei, E);
    {
        const int SMEM = (2 * 128 * LDSK + 2 * BM * LDSK) * (int)sizeof(__nv_bfloat16);
        cudaFuncSetAttribute(k_logmap_gemm,
                             cudaFuncAttributeMaxDynamicSharedMemorySize, SMEM);
        k_logmap_gemm<<<(N + BM - 1) / BM, 256, SMEM>>>(x, b, N);
    }
    {
        long long threads = (long long)N * 32;
        int grid = (int)((threads + 255) / 256);
        k_gather<<<grid, 256>>>(out, N);
    }
}

// round 8
// speedup vs baseline: 1.9209x; 1.0312x over previous
#include <cuda_runtime.h>
#include <cuda_bf16.h>
#include <cstdint>

#define DFEAT 128
#define NMAX  50000
#define NPAD  50176      // 49 * 1024
#define EMAX  600000
#define BM    64
#define LDSK  136        // smem row stride (bf16) -> 272B rows
#define NSCANB 49

// scratch (no allocations allowed) ------------------------------------------
__device__ __align__(16) float g_h[NMAX * DFEAT];     // dinv[src]-scaled features
__device__ __align__(16) int   g_cin[NPAD];
__device__ __align__(16) int   g_cout[NPAD];
__device__ __align__(16) int   g_off[NPAD + 1];
__device__ __align__(16) int   g_cur[NPAD];
__device__ __align__(16) int   g_srcs[EMAX];
__device__ __align__(16) int   g_bsum[64];
__device__ __align__(16) __nv_bfloat16 g_wh[128 * 128];
__device__ __align__(16) __nv_bfloat16 g_wl[128 * 128];

__device__ __forceinline__ void ldsm_x4(uint32_t addr, uint32_t& r0, uint32_t& r1,
                                        uint32_t& r2, uint32_t& r3) {
    asm volatile("ldmatrix.sync.aligned.m8n8.x4.shared.b16 {%0,%1,%2,%3}, [%4];"
                 : "=r"(r0), "=r"(r1), "=r"(r2), "=r"(r3) : "r"(addr));
}

__device__ __forceinline__ void mma_bf16(float c[4], const uint32_t a[4],
                                         uint32_t b0, uint32_t b1) {
    asm volatile("mma.sync.aligned.m16n8k16.row.col.f32.bf16.bf16.f32 "
                 "{%0,%1,%2,%3},{%4,%5,%6,%7},{%8,%9},{%0,%1,%2,%3};"
                 : "+f"(c[0]), "+f"(c[1]), "+f"(c[2]), "+f"(c[3])
                 : "r"(a[0]), "r"(a[1]), "r"(a[2]), "r"(a[3]), "r"(b0), "r"(b1));
}

__device__ __forceinline__ void cp_async16(uint32_t saddr, const void* gptr) {
    asm volatile("cp.async.ca.shared.global [%0], [%1], 16;"
                 :: "r"(saddr), "l"(gptr) : "memory");
}

// ---------------------------------------------------------------------------
__global__ void k_init(const float* __restrict__ W) {
    int i = blockIdx.x * blockDim.x + threadIdx.x;
    int stride = gridDim.x * blockDim.x;
    for (int idx = i; idx < NPAD; idx += stride) { g_cin[idx] = 0; g_cout[idx] = 0; }
    for (int idx = i; idx < 128 * 128; idx += stride) {
        float w = W[idx];
        __nv_bfloat16 h = __float2bfloat16_rn(w);
        g_wh[idx] = h;
        g_wl[idx] = __float2bfloat16_rn(w - __bfloat162float(h));
    }
}

__global__ void k_count(const int* __restrict__ ei, int E) {
    int e = blockIdx.x * blockDim.x + threadIdx.x;
    if (e >= E) return;
    atomicAdd(&g_cout[ei[e]], 1);        // src out-degree
    atomicAdd(&g_cin[ei[E + e]], 1);     // dst in-degree (= CSR count)
}

// ---- scan stage A: 49 blocks x 256 thr, 4 elems/thr ----
__global__ void k_scanA() {
    __shared__ int woff[8];
    int blk = blockIdx.x, t = threadIdx.x;
    int lane = t & 31, w = t >> 5;
    int base = blk * 1024 + t * 4;
    int4 c = *(const int4*)&g_cin[base];
    int s = c.x + c.y + c.z + c.w;
    int v = s;
#pragma unroll
    for (int off = 1; off < 32; off <<= 1) {
        int u = __shfl_up_sync(0xFFFFFFFFu, v, off);
        if (lane >= off) v += u;
    }
    if (lane == 31) woff[w] = v;
    __syncthreads();
    if (t == 0) {
        int run = 0;
#pragma unroll
        for (int i = 0; i < 8; i++) { int x = woff[i]; woff[i] = run; run += x; }
        g_bsum[blk] = run;
    }
    __syncthreads();
    int run = (v - s) + woff[w];
    g_off[base]     = run; run += c.x;
    g_off[base + 1] = run; run += c.y;
    g_off[base + 2] = run; run += c.z;
    g_off[base + 3] = run;
}

// ---- scan stage C: fold top-level scan in (each block redundantly scans 49 sums)
__global__ void k_scanC(int E) {
    __shared__ int boff[NSCANB];
    if (threadIdx.x == 0) {
        int run = 0;
#pragma unroll
        for (int i = 0; i < NSCANB; i++) { int x = g_bsum[i]; boff[i] = run; run += x; }
    }
    __syncthreads();
    int i = blockIdx.x * blockDim.x + threadIdx.x;
    if (i < NPAD) {
        int o = g_off[i] + boff[i >> 10];
        g_off[i] = o;
        g_cur[i] = o;
    }
    if (i == 0) g_off[NPAD] = E;
}

__global__ void k_fill(const int* __restrict__ ei, int E) {
    int e = blockIdx.x * blockDim.x + threadIdx.x;
    if (e >= E) return;
    int s = ei[e], d = ei[E + e];
    int slot = atomicAdd(&g_cur[d], 1);
    g_srcs[slot] = s;
}

// ---------------------------------------------------------------------------
// Persistent fused logmap0 + GEMM + bias + dinv[row] scale.
// W loaded once per block; loops over row-tiles with grid stride.
__global__ void __launch_bounds__(256, 2)
k_logmap_gemm(const float* __restrict__ x, const float* __restrict__ b,
              int N, int ntiles) {
    extern __shared__ __align__(16) char smraw[];
    __nv_bfloat16* swh = (__nv_bfloat16*)smraw;          // [128][LDSK]
    __nv_bfloat16* swl = swh + 128 * LDSK;
    __nv_bfloat16* sxh = swl + 128 * LDSK;               // [BM][LDSK]
    __nv_bfloat16* sxl = sxh + BM * LDSK;

    const int tid  = threadIdx.x;
    const int warp = tid >> 5, lane = tid & 31;

    // ---- W tiles via cp.async, once per block ----
    for (int c = tid; c < 2048; c += 256) {
        int row = c >> 4, col8 = (c & 15) * 8;
        uint32_t sh = (uint32_t)__cvta_generic_to_shared(&swh[row * LDSK + col8]);
        cp_async16(sh, &g_wh[row * 128 + col8]);
        uint32_t sl = (uint32_t)__cvta_generic_to_shared(&swl[row * LDSK + col8]);
        cp_async16(sl, &g_wl[row * 128 + col8]);
    }
    asm volatile("cp.async.commit_group;");

    // per-thread constant fragment geometry
    const int wm = warp & 3, wn = warp >> 2;
    const int m0 = wm * 16, n0b = wn * 64;
    const int mat = lane >> 3, mr = lane & 7;
    const int arow = m0 + mr + 8 * (mat & 1);
    const int aoff = 8 * (mat >> 1);
    uint32_t aBaseH = (uint32_t)__cvta_generic_to_shared(&sxh[arow * LDSK + aoff]);
    uint32_t aBaseL = (uint32_t)__cvta_generic_to_shared(&sxl[arow * LDSK + aoff]);
    uint32_t bBaseH[4], bBaseL[4];
#pragma unroll
    for (int g = 0; g < 4; g++) {
        int nrow = n0b + g * 16 + mr + 8 * (mat >> 1);
        int koff = 8 * (mat & 1);
        bBaseH[g] = (uint32_t)__cvta_generic_to_shared(&swh[nrow * LDSK + koff]);
        bBaseL[g] = (uint32_t)__cvta_generic_to_shared(&swl[nrow * LDSK + koff]);
    }

    bool wwait = true;
    const float4* x4 = (const float4*)x;

    for (int tile = blockIdx.x; tile < ntiles; tile += gridDim.x) {
        const int row0 = tile * BM;

        // ---- x rows: load, logmap0, split hi/lo ----
#pragma unroll
        for (int rr = 0; rr < 8; rr++) {
            int r = warp * 8 + rr;
            int row = row0 + r;
            float4 v = (row < N) ? x4[row * 32 + lane] : make_float4(0.f, 0.f, 0.f, 0.f);
            float s = v.x * v.x + v.y * v.y + v.z * v.z + v.w * v.w;
#pragma unroll
            for (int off = 16; off; off >>= 1) s += __shfl_xor_sync(0xFFFFFFFFu, s, off);
            float norm = sqrtf(s);
            float nc = fminf(fmaxf(norm, 1e-15f), 1.0f - 1e-5f);
            float scale = atanhf(nc) / fmaxf(norm, 1e-15f);
            v.x *= scale; v.y *= scale; v.z *= scale; v.w *= scale;
            __nv_bfloat16 h0 = __float2bfloat16_rn(v.x), h1 = __float2bfloat16_rn(v.y);
            __nv_bfloat16 h2 = __float2bfloat16_rn(v.z), h3 = __float2bfloat16_rn(v.w);
            __nv_bfloat16 l0 = __float2bfloat16_rn(v.x - __bfloat162float(h0));
            __nv_bfloat16 l1 = __float2bfloat16_rn(v.y - __bfloat162float(h1));
            __nv_bfloat16 l2 = __float2bfloat16_rn(v.z - __bfloat162float(h2));
            __nv_bfloat16 l3 = __float2bfloat16_rn(v.w - __bfloat162float(h3));
            int kc = lane * 4;
            __nv_bfloat162 hh0; hh0.x = h0; hh0.y = h1;
            __nv_bfloat162 hh1; hh1.x = h2; hh1.y = h3;
            __nv_bfloat162 ll0; ll0.x = l0; ll0.y = l1;
            __nv_bfloat162 ll1; ll1.x = l2; ll1.y = l3;
            *(__nv_bfloat162*)&sxh[r * LDSK + kc]     = hh0;
            *(__nv_bfloat162*)&sxh[r * LDSK + kc + 2] = hh1;
            *(__nv_bfloat162*)&sxl[r * LDSK + kc]     = ll0;
            *(__nv_bfloat162*)&sxl[r * LDSK + kc + 2] = ll1;
        }
        if (wwait) {
            asm volatile("cp.async.wait_group 0;");
            wwait = false;
        }
        __syncthreads();

        // ---- MMA mainloop (pipelined) ----
        float acc[8][4];
#pragma unroll
        for (int f = 0; f < 8; f++)
#pragma unroll
            for (int j = 0; j < 4; j++) acc[f][j] = 0.f;

        uint32_t ah[2][4], al[2][4];
        uint32_t bh[2][4], bl[2][4];

        ldsm_x4(aBaseH, ah[0][0], ah[0][1], ah[0][2], ah[0][3]);
        ldsm_x4(aBaseL, al[0][0], al[0][1], al[0][2], al[0][3]);

#pragma unroll
        for (int kk = 0; kk < 8; kk++) {
            const uint32_t kb = kk * 32;
            const int cur = kk & 1, nxt = cur ^ 1;
            ldsm_x4(bBaseH[0] + kb, bh[0][0], bh[0][1], bh[0][2], bh[0][3]);
            ldsm_x4(bBaseL[0] + kb, bl[0][0], bl[0][1], bl[0][2], bl[0][3]);
            if (kk < 7) {
                ldsm_x4(aBaseH + kb + 32, ah[nxt][0], ah[nxt][1], ah[nxt][2], ah[nxt][3]);
                ldsm_x4(aBaseL + kb + 32, al[nxt][0], al[nxt][1], al[nxt][2], al[nxt][3]);
            }
#pragma unroll
            for (int g = 0; g < 4; g++) {
                const int gb = g & 1, gn = gb ^ 1;
                if (g < 3) {
                    ldsm_x4(bBaseH[g + 1] + kb, bh[gn][0], bh[gn][1], bh[gn][2], bh[gn][3]);
                    ldsm_x4(bBaseL[g + 1] + kb, bl[gn][0], bl[gn][1], bl[gn][2], bl[gn][3]);
                }
#pragma unroll
                for (int o = 0; o < 2; o++) {
                    const int f = 2 * g + o;
                    uint32_t b0h = bh[gb][2 * o], b1h = bh[gb][2 * o + 1];
                    uint32_t b0l = bl[gb][2 * o], b1l = bl[gb][2 * o + 1];
                    mma_bf16(acc[f], ah[cur], b0h, b1h);
                    mma_bf16(acc[f], ah[cur], b0l, b1l);
                    mma_bf16(acc[f], al[cur], b0h, b1h);
                    mma_bf16(acc[f], al[cur], b0l, b1l);
                }
            }
        }
        __syncthreads();   // x smem consumed; safe to refill next tile

        // ---- epilogue: +bias, *rsqrt(deg), store ----
        int r0r = row0 + m0 + (lane >> 2);
        int r1r = r0r + 8;
        float di0 = 0.f, di1 = 0.f;
        if (r0r < N) di0 = rsqrtf(fmaxf((float)(g_cin[r0r] + g_cout[r0r]), 1.0f));
        if (r1r < N) di1 = rsqrtf(fmaxf((float)(g_cin[r1r] + g_cout[r1r]), 1.0f));
        float2* h2p = (float2*)g_h;
#pragma unroll
        for (int f = 0; f < 8; f++) {
            int c = n0b + f * 8 + 2 * (lane & 3);
            float bx = b[c], by = b[c + 1];
            if (r0r < N) {
                float2 o0;
                o0.x = (acc[f][0] + bx) * di0;
                o0.y = (acc[f][1] + by) * di0;
                h2p[(r0r * DFEAT + c) >> 1] = o0;
            }
            if (r1r < N) {
                float2 o1;
                o1.x = (acc[f][2] + bx) * di1;
                o1.y = (acc[f][3] + by) * di1;
                h2p[(r1r * DFEAT + c) >> 1] = o1;
            }
        }
    }
}

// ---------------------------------------------------------------------------
// CSR gather-sum + dinv[dst] + expmap0, one warp per node. No atomics.
__global__ void k_gather(float* __restrict__ out, int N) {
    int gw = (blockIdx.x * blockDim.x + threadIdx.x) >> 5;
    int lane = threadIdx.x & 31;
    if (gw >= N) return;
    int beg = g_off[gw], end = g_off[gw + 1];
    const float4* h4 = (const float4*)g_h;

    float4 a0 = make_float4(0.f, 0.f, 0.f, 0.f);
    float4 a1 = make_float4(0.f, 0.f, 0.f, 0.f);
    int p = beg;
    for (; p + 2 <= end; p += 2) {
        int s0 = __ldg(&g_srcs[p]);
        int s1 = __ldg(&g_srcs[p + 1]);
        float4 v0 = h4[s0 * 32 + lane];
        float4 v1 = h4[s1 * 32 + lane];
        a0.x += v0.x; a0.y += v0.y; a0.z += v0.z; a0.w += v0.w;
        a1.x += v1.x; a1.y += v1.y; a1.z += v1.z; a1.w += v1.w;
    }
    if (p < end) {
        int s0 = __ldg(&g_srcs[p]);
        float4 v0 = h4[s0 * 32 + lane];
        a0.x += v0.x; a0.y += v0.y; a0.z += v0.z; a0.w += v0.w;
    }
    float di = rsqrtf(fmaxf((float)(g_cin[gw] + g_cout[gw]), 1.0f));
    float4 acc;
    acc.x = (a0.x + a1.x) * di;
    acc.y = (a0.y + a1.y) * di;
    acc.z = (a0.z + a1.z) * di;
    acc.w = (a0.w + a1.w) * di;

    float s = acc.x * acc.x + acc.y * acc.y + acc.z * acc.z + acc.w * acc.w;
#pragma unroll
    for (int off = 16; off; off >>= 1) s += __shfl_xor_sync(0xFFFFFFFFu, s, off);
    float norm = sqrtf(s);
    float scale = tanhf(norm) / fmaxf(norm, 1e-15f);
    acc.x *= scale; acc.y *= scale; acc.z *= scale; acc.w *= scale;
    ((float4*)out)[gw * 32 + lane] = acc;
}

// ---------------------------------------------------------------------------
extern "C" void kernel_launch(void* const* d_in, const int* in_sizes, int n_in,
                              void* d_out, int out_size) {
    const float* x  = (const float*)d_in[0];
    const int*   ei = (const int*)d_in[1];
    const float* W  = (const float*)d_in[2];
    const float* b  = (const float*)d_in[3];
    float* out = (float*)d_out;

    const int N = in_sizes[0] / DFEAT;
    const int E = in_sizes[1] / 2;
    const int NB = NPAD / 1024;            // 49 scan blocks

    k_init<<<(NPAD + 255) / 256, 256>>>(W);
    k_count<<<(E + 255) / 256, 256>>>(ei, E);
    k_scanA<<<NB, 256>>>();
    k_scanC<<<(NPAD + 255) / 256, 256>>>(E);
    k_fill<<<(E + 255) / 256, 256>>>(ei, E);
    {
        const int SMEM = (2 * 128 * LDSK + 2 * BM * LDSK) * (int)sizeof(__nv_bfloat16);
        cudaFuncSetAttribute(k_logmap_gemm,
                             cudaFuncAttributeMaxDynamicSharedMemorySize, SMEM);
        const int ntiles = (N + BM - 1) / BM;
        int grid = 296;                    // 2 blocks/SM persistent
        if (grid > ntiles) grid = ntiles;
        k_logmap_gemm<<<grid, 256, SMEM>>>(x, b, N, ntiles);
    }
    {
        long long threads = (long long)N * 32;
        int grid = (int)((threads + 255) / 256);
        k_gather<<<grid, 256>>>(out, N);
    }
}